// round 14
// baseline (speedup 1.0000x reference)
#include <cuda_runtime.h>
#include <cuda_bf16.h>
#include <cuda_pipeline.h>
#include <math.h>

#define B_SZ 256
#define L_SZ 16384
#define NCHUNK 8
#define CS (L_SZ / NCHUNK)          // 2048 positions per chunk, 2 subtiles/thread
#define NPART 10                    // 6 mat entries + 3 counts + ce

// Scratch: g_part[(c*NPART + i) * B_SZ + b]  (lane-coalesced over b)
__device__ float g_part[NCHUNK * NPART * B_SZ];

__device__ __forceinline__ float frcp(float x) {
    float r;
    asm("rcp.approx.f32 %0, %1;" : "=f"(r) : "f"(x));
    return r;
}

// One token, direct rcp. Returns s4v (=1 for invalid) for the batched log.
__device__ __forceinline__ float tok1(
    float x0, float x1, float x2, float x3, int lab,
    float acc[6], unsigned& npack, float& ce)
{
    float e0 = __expf(x0), e1 = __expf(x1), e2 = __expf(x2), e3 = __expf(x3);
    float s3 = (e0 + e1) + e2;
    bool  valid = (lab != 3);
    float s4v = valid ? (s3 + e3) : 1.0f;
    float xl = (lab == 0) ? x0 : (lab == 1) ? x1 : x2;
    if (valid) ce -= xl;

    float q  = frcp(s3);
    float p0 = e0 * q, p1 = e1 * q;
    if (lab == 0)      { acc[0] += p0; acc[1] += p1; npack += 1u; }
    else if (lab == 1) { acc[2] += p0; acc[3] += p1; npack += (1u << 10); }
    else if (lab == 2) { acc[4] += p0; acc[5] += p1; npack += (1u << 20); }
    return s4v;
}

__global__ __launch_bounds__(256, 5) void k2_main(
    const float* __restrict__ pred, const int* __restrict__ labels)
{
    // SMEM staging: 2 subtiles x 4 planes x 1024 floats = 32KB.
    // Thread tid owns floats [tid*4, tid*4+4) of each plane: it reads back
    // exactly what it wrote -> cp.async completion (wait_prior) is the ONLY
    // synchronization the pipeline needs.
    __shared__ float sbuf[2][4][1024];

    const int tid = threadIdx.x;
    const int ch = blockIdx.x;
    const int b  = blockIdx.y;

    const float* P  = pred + (size_t)b * 4 * L_SZ + ch * CS;
    const int*   Lb = labels + (size_t)b * L_SZ + ch * CS;

    float acc[6];
#pragma unroll
    for (int i = 0; i < 6; ++i) acc[i] = 0.0f;
    unsigned npack = 0u;
    float ce = 0.0f;

    // Front-batch both subtiles' labels (one exposed round-trip), ballots.
    const int l0 = tid * 4;
    int4 lb0 = *reinterpret_cast<const int4*>(Lb + l0);
    int4 lb1 = *reinterpret_cast<const int4*>(Lb + 1024 + l0);
    bool av0 = (lb0.x != 3) | (lb0.y != 3) | (lb0.z != 3) | (lb0.w != 3);
    bool av1 = (lb1.x != 3) | (lb1.y != 3) | (lb1.z != 3) | (lb1.w != 3);
    unsigned bal0 = __ballot_sync(0xFFFFFFFFu, av0);
    unsigned bal1 = __ballot_sync(0xFFFFFFFFu, av1);
    // Block-wide subtile validity (barrier + OR): gates the async fetches.
    int v0 = __syncthreads_or((int)av0);
    int v1 = __syncthreads_or((int)av1);

    // Issue ALL pred bytes as register-free async copies, then compute.
    if (v0) {
#pragma unroll
        for (int p = 0; p < 4; ++p)
            __pipeline_memcpy_async(&sbuf[0][p][l0], P + p * L_SZ + l0, 16);
    }
    __pipeline_commit();
    if (v1) {
#pragma unroll
        for (int p = 0; p < 4; ++p)
            __pipeline_memcpy_async(&sbuf[1][p][l0], P + p * L_SZ + 1024 + l0, 16);
    }
    __pipeline_commit();

    // Subtile 0: wait for group 0 only; subtile 1 keeps streaming underneath.
    __pipeline_wait_prior(1);
    if (bal0) {
        float4 a0 = *reinterpret_cast<const float4*>(&sbuf[0][0][l0]);
        float4 a1 = *reinterpret_cast<const float4*>(&sbuf[0][1][l0]);
        float4 a2 = *reinterpret_cast<const float4*>(&sbuf[0][2][l0]);
        float4 a3 = *reinterpret_cast<const float4*>(&sbuf[0][3][l0]);
        float sx = tok1(a0.x, a1.x, a2.x, a3.x, lb0.x, acc, npack, ce);
        float sy = tok1(a0.y, a1.y, a2.y, a3.y, lb0.y, acc, npack, ce);
        float sz = tok1(a0.z, a1.z, a2.z, a3.z, lb0.z, acc, npack, ce);
        float sw = tok1(a0.w, a1.w, a2.w, a3.w, lb0.w, acc, npack, ce);
        ce += __logf((sx * sy) * (sz * sw));
    }

    __pipeline_wait_prior(0);
    if (bal1) {
        float4 a0 = *reinterpret_cast<const float4*>(&sbuf[1][0][l0]);
        float4 a1 = *reinterpret_cast<const float4*>(&sbuf[1][1][l0]);
        float4 a2 = *reinterpret_cast<const float4*>(&sbuf[1][2][l0]);
        float4 a3 = *reinterpret_cast<const float4*>(&sbuf[1][3][l0]);
        float sx = tok1(a0.x, a1.x, a2.x, a3.x, lb1.x, acc, npack, ce);
        float sy = tok1(a0.y, a1.y, a2.y, a3.y, lb1.y, acc, npack, ce);
        float sz = tok1(a0.z, a1.z, a2.z, a3.z, lb1.z, acc, npack, ce);
        float sw = tok1(a0.w, a1.w, a2.w, a3.w, lb1.w, acc, npack, ce);
        ce += __logf((sx * sy) * (sz * sw));
    }

    // Warp reduction: 7 floats + 1 packed int.
#pragma unroll
    for (int off = 16; off > 0; off >>= 1) {
#pragma unroll
        for (int i = 0; i < 6; ++i)
            acc[i] += __shfl_xor_sync(0xFFFFFFFFu, acc[i], off);
        ce    += __shfl_xor_sync(0xFFFFFFFFu, ce, off);
        npack += __shfl_xor_sync(0xFFFFFFFFu, npack, off);
    }

    __shared__ float sm[8][NPART];
    const int wid = tid >> 5, lane = tid & 31;
    if (lane == 0) {
#pragma unroll
        for (int i = 0; i < 6; ++i) sm[wid][i] = acc[i];
        sm[wid][6] = (float)(npack & 1023u);
        sm[wid][7] = (float)((npack >> 10) & 1023u);
        sm[wid][8] = (float)((npack >> 20) & 1023u);
        sm[wid][9] = ce;
    }
    __syncthreads();
    if (tid == 0) {
#pragma unroll
        for (int i = 0; i < NPART; ++i) {
            float s = 0.0f;
#pragma unroll
            for (int w = 0; w < 8; ++w) s += sm[w][i];
            g_part[(ch * NPART + i) * B_SZ + b] = s;
        }
    }
}

// ---------------- K3: finalize ----------------
__global__ __launch_bounds__(1024) void k3_final(float* __restrict__ out) {
    if (blockIdx.x != 0) return;

    const int tid = threadIdx.x;
    const int g   = tid >> 8;       // 0..3 -> two chunks each
    const int b   = tid & 255;      // row

    float v[2 * NPART];
#pragma unroll
    for (int cc = 0; cc < 2; ++cc) {
        const int c = g * 2 + cc;
#pragma unroll
        for (int i = 0; i < NPART; ++i)
            v[cc * NPART + i] = g_part[(c * NPART + i) * B_SZ + b];
    }

    __shared__ float smg[4][NPART][B_SZ];    // 40KB, b lane-major: conflict-free
#pragma unroll
    for (int i = 0; i < NPART; ++i)
        smg[g][i][b] = v[i] + v[NPART + i];
    __syncthreads();

    __shared__ double s_dmi[B_SZ];
    __shared__ double s_ce[B_SZ];
    __shared__ double s_cnt[B_SZ];

    if (g == 0) {
        float m[NPART];
#pragma unroll
        for (int i = 0; i < NPART; ++i)
            m[i] = (smg[0][i][b] + smg[1][i][b]) + (smg[2][i][b] + smg[3][i][b]);

        float n0 = m[6], n1 = m[7], n2 = m[8], ce = m[9];
        float cnt = n0 + n1 + n2;   // == j (pads are a suffix, always present)

        double a0 = m[0], a1 = m[1], a2 = (double)n0 - m[0] - m[1];
        double b0 = m[2], b1 = m[3], b2 = (double)n1 - m[2] - m[3];
        double c0 = m[4], c1 = m[5], c2 = (double)n2 - m[4] - m[5];

        double det = a0 * (b1 * c2 - b2 * c1)
                   - a1 * (b0 * c2 - b2 * c0)
                   + a2 * (b0 * c1 - b1 * c0);
        double jf = (double)cnt;
        double dets = det / (jf * jf * jf);

        float arg = (float)fabs(dets) + 1e-3f;
        float lg = __logf(arg);
        float dmi = (dets < 0.0) ? lg : -lg;

        s_dmi[b] = (double)dmi;
        s_ce[b]  = (double)ce;
        s_cnt[b] = (double)cnt;
    }
    __syncthreads();

    for (int s = 128; s > 0; s >>= 1) {
        if (tid < s) {
            s_dmi[tid] += s_dmi[tid + s];
            s_ce[tid]  += s_ce[tid + s];
            s_cnt[tid] += s_cnt[tid + s];
        }
        __syncthreads();
    }
    if (tid == 0) {
        double loss = 0.1 * (s_dmi[0] / (double)B_SZ) + s_ce[0] / s_cnt[0];
        out[0] = (float)loss;
    }
}

extern "C" void kernel_launch(void* const* d_in, const int* in_sizes, int n_in,
                              void* d_out, int out_size) {
    const float* pred;
    const int*   labels;
    if (in_sizes[0] == B_SZ * 4 * L_SZ) {
        pred   = (const float*)d_in[0];
        labels = (const int*)d_in[1];
    } else {
        pred   = (const float*)d_in[1];
        labels = (const int*)d_in[0];
    }
    float* out = (float*)d_out;

    dim3 g2(NCHUNK, B_SZ);
    k2_main<<<g2, 256>>>(pred, labels);
    k3_final<<<160, 1024>>>(out);
}